// round 1
// baseline (speedup 1.0000x reference)
#include <cuda_runtime.h>
#include <math.h>

#define CONF_TH 0.25f
#define NMS_TH  0.35f

static constexpr int N_IMG = 64;
static constexpr int HW    = 1024;   // 32*32
static constexpr int NCH   = 85;
static constexpr int NCLS  = 80;

// dynamic smem layout (bytes):
//  boxes0  float4[1024]   @      0  (16384)
//  cls0    float [1024]   @  16384  ( 4096)
//  skey    float [1024]   @  20480  ( 4096)
//  sidx    int   [1024]   @  24576  ( 4096)
//  sbox    float4[1024]   @  28672  (16384)
//  sarea   float [1024]   @  45056  ( 4096)
//  scls    float [1024]   @  49152  ( 4096)
//  mat     u32[1024*32]   @  53248  (131072)
//  keepW   u32[32]        @ 184320  (  128)
//  Ksh     int            @ 184448  (    4)
static constexpr int SMEM_BYTES = 184464;

__global__ __launch_bounds__(1024, 1)
void fastestdet_kernel(const float* __restrict__ in, float* __restrict__ out)
{
    extern __shared__ unsigned char smem_raw[];
    float4*   boxes0 = (float4*)(smem_raw);
    float*    cls0   = (float*) (smem_raw + 16384);
    float*    skey   = (float*) (smem_raw + 20480);
    int*      sidx   = (int*)   (smem_raw + 24576);
    float4*   sbox   = (float4*)(smem_raw + 28672);
    float*    sarea  = (float*) (smem_raw + 45056);
    float*    scls   = (float*) (smem_raw + 49152);
    unsigned* mat    = (unsigned*)(smem_raw + 53248);
    unsigned* keepW  = (unsigned*)(smem_raw + 184320);
    int*      Ksh    = (int*)   (smem_raw + 184448);

    const int n = blockIdx.x;
    const int t = threadIdx.x;

    // ---------------- decode (thread = pixel) ----------------
    const float* base = in + (size_t)n * NCH * HW + t;

    float pobj = base[0];
    float r0 = base[1 * HW];
    float r1 = base[2 * HW];
    float r2 = base[3 * HW];
    float r3 = base[4 * HW];

    float best = -INFINITY;
    int   bi   = 0;
    #pragma unroll 10
    for (int c = 0; c < NCLS; c++) {
        float v = base[(5 + c) * HW];
        if (v > best) { best = v; bi = c; }   // first-occurrence argmax
    }
    float score = pobj * best;

    float gx = (float)(t & 31);
    float gy = (float)(t >> 5);
    float bcx = (tanhf(r0) + gx) * (1.0f / 32.0f);
    float bcy = (tanhf(r1) + gy) * (1.0f / 32.0f);
    float bw  = 1.0f / (1.0f + expf(-r2));
    float bh  = 1.0f / (1.0f + expf(-r3));

    float x1 = bcx - 0.5f * bw;
    float y1 = bcy - 0.5f * bh;
    float x2 = bcx + 0.5f * bw;
    float y2 = bcy + 0.5f * bh;

    float* ob = out + ((size_t)n * HW + t) * 6;
    ob[0] = x1; ob[1] = y1; ob[2] = x2; ob[3] = y2;
    ob[4] = score; ob[5] = (float)bi;

    boxes0[t] = make_float4(x1, y1, x2, y2);
    cls0[t]   = (float)bi;
    skey[t]   = score;
    sidx[t]   = t;
    if (t == 0) *Ksh = 0;
    __syncthreads();

    // ---------------- bitonic sort: (score desc, idx asc) ----------------
    for (int k = 2; k <= 1024; k <<= 1) {
        for (int j = k >> 1; j > 0; j >>= 1) {
            int ixj = t ^ j;
            if (ixj > t) {
                float ka = skey[t], kb = skey[ixj];
                int   ia = sidx[t], ib = sidx[ixj];
                bool before = (ka > kb) || (ka == kb && ia < ib); // a before b in final order
                bool up = ((t & k) == 0);
                if (before != up) {
                    skey[t] = kb; skey[ixj] = ka;
                    sidx[t] = ib; sidx[ixj] = ia;
                }
            }
            __syncthreads();
        }
    }

    // ---------------- candidate count K + gather sorted boxes ----------------
    if (skey[t] > CONF_TH) atomicMax(Ksh, t + 1);   // sorted desc -> prefix
    {
        int o = sidx[t];
        float4 b4 = boxes0[o];
        sbox[t]  = b4;
        sarea[t] = (b4.z - b4.x) * (b4.w - b4.y);
        scls[t]  = cls0[o];
    }
    __syncthreads();
    const int K = *Ksh;

    // ---------------- suppression matrix (lower-triangle words) ----------------
    const int wid  = t >> 5;
    const int lane = t & 31;
    for (int i = wid; i < K; i += 32) {
        float4 ib = sbox[i];
        float iarea = sarea[i];
        float icls  = scls[i];
        int cmax = i >> 5;
        for (int c = 0; c <= cmax; c++) {
            int j = c * 32 + lane;
            float4 jb = sbox[j];
            float iw = fminf(ib.z, jb.z) - fmaxf(ib.x, jb.x);
            float ih = fminf(ib.w, jb.w) - fmaxf(ib.y, jb.y);
            iw = fmaxf(iw, 0.0f);
            ih = fmaxf(ih, 0.0f);
            float inter = iw * ih;
            float uni   = iarea + sarea[j] - inter + 1e-9f;  // > 0 always
            bool supp = (inter > NMS_TH * uni) && (icls == scls[j]);
            unsigned bal = __ballot_sync(0xffffffffu, supp);
            if (lane == 0) mat[i * 32 + c] = bal;
        }
    }
    __syncthreads();

    // ---------------- sequential greedy scan (warp 0) ----------------
    if (wid == 0) {
        unsigned keep = 0;  // lane owns sorted positions [lane*32, lane*32+32)
        for (int i = 0; i < K; i++) {
            unsigned r = mat[i * 32 + lane];  // words > i/32 may be garbage: keep there is 0
            bool any = __any_sync(0xffffffffu, (r & keep) != 0u);
            if (!any && lane == (i >> 5)) keep |= 1u << (i & 31);
        }
        keepW[lane] = keep;
    }
    __syncthreads();

    // ---------------- scatter keep back to original order ----------------
    unsigned bit = (keepW[t >> 5] >> (t & 31)) & 1u;
    out[(size_t)N_IMG * HW * 6 + (size_t)n * HW + sidx[t]] = (float)bit;
}

extern "C" void kernel_launch(void* const* d_in, const int* in_sizes, int n_in,
                              void* d_out, int out_size)
{
    const float* in = (const float*)d_in[0];
    float* out = (float*)d_out;
    cudaFuncSetAttribute(fastestdet_kernel,
                         cudaFuncAttributeMaxDynamicSharedMemorySize, SMEM_BYTES);
    fastestdet_kernel<<<N_IMG, 1024, SMEM_BYTES>>>(in, out);
}

// round 2
// speedup vs baseline: 1.1481x; 1.1481x over previous
#include <cuda_runtime.h>
#include <math.h>

#define CONF_TH 0.25f
#define NMS_TH  0.35f

static constexpr int N_IMG = 64;
static constexpr int HW    = 1024;   // 32*32
static constexpr int NCH   = 85;
static constexpr int NCLS  = 80;
static constexpr int MROW  = 33;     // padded mat row stride (words) -> conflict-free column reads

// smem layout (bytes):
//  key64   u64 [1024]   @      0  (  8192)
//  boxes0  float4[1024] @   8192  ( 16384)
//  cls0    float [1024] @  24576  (  4096)
//  sbox    float4[1024] @  28672  ( 16384)
//  sac     float2[1024] @  45056  (  8192)   (area, cls)
//  sidx    int   [1024] @  53248  (  4096)
//  mat     u32[1024*33] @  57344  (135168)
//  keepW   u32[32]      @ 192512  (   128)
//  Ksh     int          @ 192640  (     4)
static constexpr int SMEM_BYTES = 192644;

__device__ __forceinline__ unsigned long long bitonic_shfl_step(
    unsigned long long key, int j, bool up, int t)
{
    unsigned long long p = __shfl_xor_sync(0xffffffffu, key, j);
    bool low     = ((t & j) == 0);
    bool takeMin = (low == up);
    bool swap    = takeMin ? (p < key) : (p > key);
    return swap ? p : key;
}

__global__ __launch_bounds__(1024, 1)
void fastestdet_kernel(const float* __restrict__ in, float* __restrict__ out)
{
    extern __shared__ unsigned char smem_raw[];
    unsigned long long* key64 = (unsigned long long*)(smem_raw);
    float4*   boxes0 = (float4*)(smem_raw + 8192);
    float*    cls0   = (float*) (smem_raw + 24576);
    float4*   sbox   = (float4*)(smem_raw + 28672);
    float2*   sac    = (float2*)(smem_raw + 45056);
    int*      sidx   = (int*)   (smem_raw + 53248);
    unsigned* mat    = (unsigned*)(smem_raw + 57344);
    unsigned* keepW  = (unsigned*)(smem_raw + 192512);
    int*      Ksh    = (int*)   (smem_raw + 192640);

    const int n = blockIdx.x;
    const int t = threadIdx.x;

    // ---------------- decode (thread = pixel) ----------------
    const float* base = in + (size_t)n * NCH * HW + t;

    float pobj = base[0];
    float r0 = base[1 * HW];
    float r1 = base[2 * HW];
    float r2 = base[3 * HW];
    float r3 = base[4 * HW];

    // 4-way ILP argmax over 80 classes (first-occurrence semantics, tie-aware merge)
    float b0 = -INFINITY, b1 = -INFINITY, b2 = -INFINITY, b3 = -INFINITY;
    int   j0 = 0, j1 = 1, j2 = 2, j3 = 3;
    #pragma unroll
    for (int c = 0; c < NCLS; c += 4) {
        float v0 = base[(5 + c + 0) * HW];
        float v1 = base[(5 + c + 1) * HW];
        float v2 = base[(5 + c + 2) * HW];
        float v3 = base[(5 + c + 3) * HW];
        if (v0 > b0) { b0 = v0; j0 = c + 0; }
        if (v1 > b1) { b1 = v1; j1 = c + 1; }
        if (v2 > b2) { b2 = v2; j2 = c + 2; }
        if (v3 > b3) { b3 = v3; j3 = c + 3; }
    }
    // tie-aware merges (first occurrence = smallest index)
    float bestA; int idxA;
    if (b1 > b0 || (b1 == b0 && j1 < j0)) { bestA = b1; idxA = j1; } else { bestA = b0; idxA = j0; }
    float bestB; int idxB;
    if (b3 > b2 || (b3 == b2 && j3 < j2)) { bestB = b3; idxB = j3; } else { bestB = b2; idxB = j2; }
    float best; int bi;
    if (bestB > bestA || (bestB == bestA && idxB < idxA)) { best = bestB; bi = idxB; }
    else { best = bestA; bi = idxA; }

    float score = pobj * best;

    float gx = (float)(t & 31);
    float gy = (float)(t >> 5);
    float bcx = (tanhf(r0) + gx) * (1.0f / 32.0f);
    float bcy = (tanhf(r1) + gy) * (1.0f / 32.0f);
    float bw  = 1.0f / (1.0f + expf(-r2));
    float bh  = 1.0f / (1.0f + expf(-r3));

    float x1 = bcx - 0.5f * bw;
    float y1 = bcy - 0.5f * bh;
    float x2 = bcx + 0.5f * bw;
    float y2 = bcy + 0.5f * bh;

    float* ob = out + ((size_t)n * HW + t) * 6;
    ob[0] = x1; ob[1] = y1; ob[2] = x2; ob[3] = y2;
    ob[4] = score; ob[5] = (float)bi;

    boxes0[t] = make_float4(x1, y1, x2, y2);
    cls0[t]   = (float)bi;

    // packed sort key: ascending u64 order == (score desc, idx asc)
    unsigned u = __float_as_uint(score);
    u = (u & 0x80000000u) ? ~u : (u | 0x80000000u);   // sortable ascending
    unsigned k32 = ~u;                                 // invert -> descending score
    unsigned long long key = ((unsigned long long)k32 << 32) | (unsigned)t;

    if (t == 0) *Ksh = 0;
    if (t < 32) keepW[t] = 0;

    // ---------------- bitonic sort (hybrid shfl + smem), ascending on key ----------------
    // stages k=2..32: pure register, intra-warp
    #pragma unroll
    for (int k = 2; k <= 32; k <<= 1) {
        #pragma unroll
        for (int j = k >> 1; j >= 1; j >>= 1) {
            bool up = ((t & k) == 0);
            key = bitonic_shfl_step(key, j, up, t);
        }
    }
    key64[t] = key;
    __syncthreads();

    // stages k=64..1024: smem steps for j>=32, then 5 shfl steps
    #pragma unroll
    for (int k = 64; k <= 1024; k <<= 1) {
        bool up = ((t & k) == 0);
        for (int j = k >> 1; j >= 32; j >>= 1) {
            if ((t & j) == 0) {                      // single writer per pair
                unsigned long long a = key64[t];
                unsigned long long b = key64[t ^ j];
                bool swap = up ? (b < a) : (b > a);
                if (swap) { key64[t] = b; key64[t ^ j] = a; }
            }
            __syncthreads();
        }
        key = key64[t];
        #pragma unroll
        for (int j = 16; j >= 1; j >>= 1)
            key = bitonic_shfl_step(key, j, up, t);
        key64[t] = key;
        __syncthreads();
    }

    // ---------------- K count + gather sorted boxes ----------------
    {
        unsigned sk32 = (unsigned)(key >> 32);
        int o = (int)(key & 0xffffffffu);
        bool cand = sk32 < 0x417FFFFFu;   // == (score > 0.25f), in key space
        unsigned cb = __ballot_sync(0xffffffffu, cand);
        if ((t & 31) == 0 && cb) atomicAdd(Ksh, __popc(cb));

        float4 b4 = boxes0[o];
        sbox[t] = b4;
        sac[t]  = make_float2((b4.z - b4.x) * (b4.w - b4.y), cls0[o]);
        sidx[t] = o;
    }
    __syncthreads();
    const int K = *Ksh;

    // ---------------- suppression matrix (lower-triangle words, row stride 33) ----------------
    const int wid  = t >> 5;
    const int lane = t & 31;
    for (int i = wid; i < K; i += 32) {
        float4 ib = sbox[i];
        float2 ia = sac[i];
        int cmax = i >> 5;
        for (int c = 0; c <= cmax; c++) {
            int j = c * 32 + lane;
            float4 jb = sbox[j];
            float2 ja = sac[j];
            float iw = fminf(ib.z, jb.z) - fmaxf(ib.x, jb.x);
            float ih = fminf(ib.w, jb.w) - fmaxf(ib.y, jb.y);
            iw = fmaxf(iw, 0.0f);
            ih = fmaxf(ih, 0.0f);
            float inter = iw * ih;
            float uni   = ia.x + ja.x - inter + 1e-9f;   // > 0 always
            bool supp = (inter > NMS_TH * uni) && (ia.y == ja.y);
            unsigned bal = __ballot_sync(0xffffffffu, supp);
            if (lane == 0) mat[i * MROW + c] = bal;
        }
    }
    __syncthreads();

    // ---------------- blocked greedy scan (warp 0) ----------------
    if (t < 32) {
        const int nb = (K + 31) >> 5;
        for (int b = 0; b < nb; b++) {
            // phase A: inter-block suppression, lane = row-in-block (conflict-free: stride 33)
            int i = b * 32 + lane;
            unsigned sup = 0;
            for (int c = 0; c < b; c++)
                sup |= mat[i * MROW + c] & keepW[c];
            bool candr = (i < K) && (sup == 0);
            unsigned candmask = __ballot_sync(0xffffffffu, candr);

            // phase B: single-lane all-register serial recurrence, 12-cyc/row chain
            if (lane == 0) {
                const unsigned* rowp = &mat[(size_t)b * 32 * MROW + b];
                unsigned rs = 0;            // removed >> il
                unsigned cs = candmask;     // candmask >> il
                unsigned kb = 0;
                #pragma unroll
                for (int ch = 0; ch < 2; ch++) {
                    unsigned d[16];
                    #pragma unroll
                    for (int q = 0; q < 16; q++)
                        d[q] = rowp[(ch * 16 + q) * MROW];
                    #pragma unroll
                    for (int q = 0; q < 16; q++) {
                        int il = ch * 16 + q;
                        int sh = (il + 1 < 32) ? (il + 1) : 31;  // row 31's dss is dead
                        d[q] >>= sh;
                    }
                    #pragma unroll
                    for (int q = 0; q < 16; q++) {
                        int il = ch * 16 + q;
                        unsigned m  = (~rs) & cs & 1u;       // keep this row?
                        unsigned mm = 0u - m;
                        kb |= m << il;                        // off critical path
                        rs = (rs >> 1) | (d[q] & mm);         // removed' >> (il+1)
                        cs >>= 1;                             // off critical path
                    }
                }
                keepW[b] = kb;
            }
            __syncwarp(0xffffffffu);
        }
    }
    __syncthreads();

    // ---------------- scatter keep back to original order ----------------
    unsigned bit = (keepW[t >> 5] >> (t & 31)) & 1u;
    out[(size_t)N_IMG * HW * 6 + (size_t)n * HW + sidx[t]] = (float)bit;
}

extern "C" void kernel_launch(void* const* d_in, const int* in_sizes, int n_in,
                              void* d_out, int out_size)
{
    const float* in = (const float*)d_in[0];
    float* out = (float*)d_out;
    cudaFuncSetAttribute(fastestdet_kernel,
                         cudaFuncAttributeMaxDynamicSharedMemorySize, SMEM_BYTES);
    fastestdet_kernel<<<N_IMG, 1024, SMEM_BYTES>>>(in, out);
}

// round 3
// speedup vs baseline: 1.2817x; 1.1163x over previous
#include <cuda_runtime.h>
#include <math.h>

#define CONF_TH 0.25f
#define NMS_TH  0.35f

static constexpr int N_IMG = 64;
static constexpr int HW    = 1024;   // 32*32
static constexpr int NCH   = 85;
static constexpr int NCLS  = 80;

// smem layout (bytes):
//  key64   u64 [1024]   @      0  (  8192)
//  boxes0  float4[1024] @   8192  ( 16384)
//  cls0    int  [1024]  @  24576  (  4096)
//  sbox    float4[1024] @  28672  ( 16384)
//  sarea   float[1024]  @  45056  (  4096)
//  scls    int  [1024]  @  49152  (  4096)
//  sidx    int  [1024]  @  53248  (  4096)
//  keepS   u32  [1024]  @  57344  (  4096)
static constexpr int SMEM_BYTES = 61440;

__device__ __forceinline__ unsigned long long bitonic_shfl_step(
    unsigned long long key, int j, bool up, int t)
{
    unsigned long long p = __shfl_xor_sync(0xffffffffu, key, j);
    bool low     = ((t & j) == 0);
    bool takeMin = (low == up);
    bool swap    = takeMin ? (p < key) : (p > key);
    return swap ? p : key;
}

__global__ __launch_bounds__(1024, 1)
void fastestdet_kernel(const float* __restrict__ in, float* __restrict__ out)
{
    extern __shared__ unsigned char smem_raw[];
    unsigned long long* key64 = (unsigned long long*)(smem_raw);
    float4*   boxes0 = (float4*)(smem_raw + 8192);
    int*      cls0   = (int*)   (smem_raw + 24576);
    float4*   sbox   = (float4*)(smem_raw + 28672);
    float*    sarea  = (float*) (smem_raw + 45056);
    int*      scls   = (int*)   (smem_raw + 49152);
    int*      sidx   = (int*)   (smem_raw + 53248);
    unsigned* keepS  = (unsigned*)(smem_raw + 57344);

    const int n = blockIdx.x;
    const int t = threadIdx.x;

    // ---------------- decode (thread = pixel) ----------------
    const float* base = in + (size_t)n * NCH * HW + t;

    float pobj = base[0];
    float r0 = base[1 * HW];
    float r1 = base[2 * HW];
    float r2 = base[3 * HW];
    float r3 = base[4 * HW];

    // 4-way ILP argmax over 80 classes (first-occurrence semantics, tie-aware merge)
    float b0 = -INFINITY, b1 = -INFINITY, b2 = -INFINITY, b3 = -INFINITY;
    int   j0 = 0, j1 = 1, j2 = 2, j3 = 3;
    #pragma unroll
    for (int c = 0; c < NCLS; c += 4) {
        float v0 = base[(5 + c + 0) * HW];
        float v1 = base[(5 + c + 1) * HW];
        float v2 = base[(5 + c + 2) * HW];
        float v3 = base[(5 + c + 3) * HW];
        if (v0 > b0) { b0 = v0; j0 = c + 0; }
        if (v1 > b1) { b1 = v1; j1 = c + 1; }
        if (v2 > b2) { b2 = v2; j2 = c + 2; }
        if (v3 > b3) { b3 = v3; j3 = c + 3; }
    }
    float bestA; int idxA;
    if (b1 > b0 || (b1 == b0 && j1 < j0)) { bestA = b1; idxA = j1; } else { bestA = b0; idxA = j0; }
    float bestB; int idxB;
    if (b3 > b2 || (b3 == b2 && j3 < j2)) { bestB = b3; idxB = j3; } else { bestB = b2; idxB = j2; }
    float best; int bi;
    if (bestB > bestA || (bestB == bestA && idxB < idxA)) { best = bestB; bi = idxB; }
    else { best = bestA; bi = idxA; }

    float score = pobj * best;

    float gx = (float)(t & 31);
    float gy = (float)(t >> 5);
    float bcx = (tanhf(r0) + gx) * (1.0f / 32.0f);
    float bcy = (tanhf(r1) + gy) * (1.0f / 32.0f);
    float bw  = 1.0f / (1.0f + expf(-r2));
    float bh  = 1.0f / (1.0f + expf(-r3));

    float x1 = bcx - 0.5f * bw;
    float y1 = bcy - 0.5f * bh;
    float x2 = bcx + 0.5f * bw;
    float y2 = bcy + 0.5f * bh;

    float* ob = out + ((size_t)n * HW + t) * 6;
    ob[0] = x1; ob[1] = y1; ob[2] = x2; ob[3] = y2;
    ob[4] = score; ob[5] = (float)bi;

    boxes0[t] = make_float4(x1, y1, x2, y2);
    cls0[t]   = bi;

    // packed sort key (50 bits used), ascending u64 order ==
    //   candidates first, then by (cls asc, score desc, idx asc)
    bool cand = score > CONF_TH;
    unsigned u = __float_as_uint(score);
    u = (u & 0x80000000u) ? ~u : (u | 0x80000000u);   // ascending-sortable
    unsigned k32 = ~u;                                 // descending score
    unsigned long long key =
          ((unsigned long long)(cand ? 0u : 1u) << 49)
        | ((unsigned long long)(unsigned)bi    << 42)
        | ((unsigned long long)k32             << 10)
        | (unsigned)t;

    // ---------------- bitonic sort (hybrid shfl + smem), ascending ----------------
    #pragma unroll
    for (int k = 2; k <= 32; k <<= 1) {
        #pragma unroll
        for (int j = k >> 1; j >= 1; j >>= 1) {
            bool up = ((t & k) == 0);
            key = bitonic_shfl_step(key, j, up, t);
        }
    }
    key64[t] = key;
    __syncthreads();

    #pragma unroll
    for (int k = 64; k <= 1024; k <<= 1) {
        bool up = ((t & k) == 0);
        for (int j = k >> 1; j >= 32; j >>= 1) {
            if ((t & j) == 0) {                      // single writer per pair
                unsigned long long a = key64[t];
                unsigned long long b = key64[t ^ j];
                bool swap = up ? (b < a) : (b > a);
                if (swap) { key64[t] = b; key64[t ^ j] = a; }
            }
            __syncthreads();
        }
        key = key64[t];
        #pragma unroll
        for (int j = 16; j >= 1; j >>= 1)
            key = bitonic_shfl_step(key, j, up, t);
        key64[t] = key;
        __syncthreads();
    }

    // ---------------- gather sorted arrays ----------------
    bool myCand;
    int  myCls;
    {
        int o = (int)(key & 0x3FFu);
        myCand = ((key >> 49) & 1ull) == 0ull;
        myCls  = (int)((key >> 42) & 0x7Fu);
        float4 b4 = boxes0[o];
        sbox[t]  = b4;
        sarea[t] = (b4.z - b4.x) * (b4.w - b4.y);
        scls[t]  = myCand ? myCls : -1;   // sentinel ends candidate segments
        sidx[t]  = o;
        keepS[t] = 0u;
    }
    __syncthreads();

    // ---------------- per-class greedy NMS (thread = segment head) ----------------
    {
        bool head = myCand && (t == 0 || scls[t - 1] != myCls);
        if (head) {
            const int c = myCls;
            keepS[t] = 1u;                              // highest-scored of class: kept
            for (int i = t + 1; i < HW && scls[i] == c; i++) {
                float4 bi4 = sbox[i];
                float  ai  = sarea[i];
                bool suppressed = false;
                for (int j = t; j < i; j++) {
                    if (keepS[j]) {
                        float4 bj = sbox[j];
                        float iw = fminf(bi4.z, bj.z) - fmaxf(bi4.x, bj.x);
                        float ih = fminf(bi4.w, bj.w) - fmaxf(bi4.y, bj.y);
                        iw = fmaxf(iw, 0.0f);
                        ih = fmaxf(ih, 0.0f);
                        float inter = iw * ih;
                        float uni   = ai + sarea[j] - inter + 1e-9f;   // > 0 always
                        if (inter > NMS_TH * uni) { suppressed = true; break; }
                    }
                }
                keepS[i] = suppressed ? 0u : 1u;
            }
        }
    }
    __syncthreads();

    // ---------------- scatter keep back to original order ----------------
    out[(size_t)N_IMG * HW * 6 + (size_t)n * HW + sidx[t]] = (float)keepS[t];
}

extern "C" void kernel_launch(void* const* d_in, const int* in_sizes, int n_in,
                              void* d_out, int out_size)
{
    const float* in = (const float*)d_in[0];
    float* out = (float*)d_out;
    cudaFuncSetAttribute(fastestdet_kernel,
                         cudaFuncAttributeMaxDynamicSharedMemorySize, SMEM_BYTES);
    fastestdet_kernel<<<N_IMG, 1024, SMEM_BYTES>>>(in, out);
}

// round 4
// speedup vs baseline: 2.8289x; 2.2072x over previous
#include <cuda_runtime.h>
#include <math.h>

#define CONF_TH 0.25f
#define NMS_TH  0.35f
#define FULL    0xffffffffu

static constexpr int N_IMG = 64;
static constexpr int HW    = 1024;   // 32*32
static constexpr int NCH   = 85;
static constexpr int NCLS  = 80;

__device__ __forceinline__ unsigned long long bitonic_shfl_step(
    unsigned long long key, int j, bool up, int t)
{
    unsigned long long p = __shfl_xor_sync(FULL, key, j);
    bool low     = ((t & j) == 0);
    bool takeMin = (low == up);
    bool swap    = takeMin ? (p < key) : (p > key);
    return swap ? p : key;
}

__global__ __launch_bounds__(1024, 1)
void fastestdet_kernel(const float* __restrict__ in, float* __restrict__ out)
{
    __shared__ float4             sbox[HW];      // box by original pos
    __shared__ unsigned long long list[HW];      // class-segmented candidate keys
    __shared__ unsigned           keepS[HW];     // keep flag by original pos
    __shared__ unsigned           state[HW];     // generic-path state (0/1/2)
    __shared__ unsigned           cnt[NCLS];     // per-class candidate count
    __shared__ unsigned           segb[NCLS];    // per-class segment base
    __shared__ unsigned           curs[NCLS];    // scatter cursor

    const int n    = blockIdx.x;
    const int t    = threadIdx.x;
    const int lane = t & 31;
    const int wid  = t >> 5;

    // ---------------- decode (thread = pixel) ----------------
    const float* base = in + (size_t)n * NCH * HW + t;

    float pobj = base[0];
    float r0 = base[1 * HW];
    float r1 = base[2 * HW];
    float r2 = base[3 * HW];
    float r3 = base[4 * HW];

    // 4-way ILP argmax over 80 classes (first-occurrence semantics)
    float b0 = -INFINITY, b1 = -INFINITY, b2 = -INFINITY, b3 = -INFINITY;
    int   j0 = 0, j1 = 1, j2 = 2, j3 = 3;
    #pragma unroll
    for (int c = 0; c < NCLS; c += 4) {
        float v0 = base[(5 + c + 0) * HW];
        float v1 = base[(5 + c + 1) * HW];
        float v2 = base[(5 + c + 2) * HW];
        float v3 = base[(5 + c + 3) * HW];
        if (v0 > b0) { b0 = v0; j0 = c + 0; }
        if (v1 > b1) { b1 = v1; j1 = c + 1; }
        if (v2 > b2) { b2 = v2; j2 = c + 2; }
        if (v3 > b3) { b3 = v3; j3 = c + 3; }
    }
    float bestA; int idxA;
    if (b1 > b0 || (b1 == b0 && j1 < j0)) { bestA = b1; idxA = j1; } else { bestA = b0; idxA = j0; }
    float bestB; int idxB;
    if (b3 > b2 || (b3 == b2 && j3 < j2)) { bestB = b3; idxB = j3; } else { bestB = b2; idxB = j2; }
    float best; int bi;
    if (bestB > bestA || (bestB == bestA && idxB < idxA)) { best = bestB; bi = idxB; }
    else { best = bestA; bi = idxA; }

    float score = pobj * best;

    float gx = (float)(t & 31);
    float gy = (float)(t >> 5);
    float bcx = (tanhf(r0) + gx) * (1.0f / 32.0f);
    float bcy = (tanhf(r1) + gy) * (1.0f / 32.0f);
    float bw  = 1.0f / (1.0f + expf(-r2));
    float bh  = 1.0f / (1.0f + expf(-r3));

    float x1 = bcx - 0.5f * bw;
    float y1 = bcy - 0.5f * bh;
    float x2 = bcx + 0.5f * bw;
    float y2 = bcy + 0.5f * bh;

    float* ob = out + ((size_t)n * HW + t) * 6;
    ob[0] = x1; ob[1] = y1; ob[2] = x2; ob[3] = y2;
    ob[4] = score; ob[5] = (float)bi;

    sbox[t]  = make_float4(x1, y1, x2, y2);
    keepS[t] = 0u;
    state[t] = 0u;
    if (t < NCLS) cnt[t] = 0u;

    // candidate key: ascending u64 == (score desc, idx asc) within a class
    bool cand = score > CONF_TH;
    unsigned u = __float_as_uint(score);
    u = (u & 0x80000000u) ? ~u : (u | 0x80000000u);       // ascending-sortable
    unsigned long long key = ((unsigned long long)(~u) << 10) | (unsigned)t;

    __syncthreads();

    // ---------------- pass 1: per-class counts ----------------
    if (cand) atomicAdd(&cnt[bi], 1u);
    __syncthreads();

    // ---------------- exclusive prefix over 80 counts (warp 0) ----------------
    if (t < 32) {
        unsigned c0 = cnt[t];
        unsigned c1 = (t + 32 < NCLS) ? cnt[t + 32] : 0u;
        unsigned c2 = (t + 64 < NCLS) ? cnt[t + 64] : 0u;

        unsigned x = c0;
        #pragma unroll
        for (int d = 1; d < 32; d <<= 1) { unsigned y = __shfl_up_sync(FULL, x, d); if (lane >= d) x += y; }
        unsigned e0 = x - c0;
        unsigned tot0 = __shfl_sync(FULL, x, 31);

        x = c1;
        #pragma unroll
        for (int d = 1; d < 32; d <<= 1) { unsigned y = __shfl_up_sync(FULL, x, d); if (lane >= d) x += y; }
        unsigned e1 = tot0 + x - c1;
        unsigned tot1 = tot0 + __shfl_sync(FULL, x, 31);

        x = c2;
        #pragma unroll
        for (int d = 1; d < 32; d <<= 1) { unsigned y = __shfl_up_sync(FULL, x, d); if (lane >= d) x += y; }
        unsigned e2 = tot1 + x - c2;

        segb[t] = e0;  curs[t] = e0;
        if (t + 32 < NCLS) { segb[t + 32] = e1; curs[t + 32] = e1; }
        if (t + 64 < NCLS) { segb[t + 64] = e2; curs[t + 64] = e2; }
    }
    __syncthreads();

    // ---------------- pass 2: scatter keys into class segments ----------------
    if (cand) {
        unsigned r = atomicAdd(&curs[bi], 1u);
        list[r] = key;
    }
    __syncthreads();

    // ---------------- warp-per-class greedy NMS (no barriers) ----------------
    for (int c = wid; c < NCLS; c += 32) {
        int m  = (int)cnt[c];
        if (m == 0) continue;
        int bs = (int)segb[c];

        if (m <= 32) {
            // load members (pad with +inf keys), full-warp bitonic sort ascending
            unsigned long long kk = (lane < m) ? list[bs + lane] : ~0ull;
            #pragma unroll
            for (int k = 2; k <= 32; k <<= 1) {
                #pragma unroll
                for (int j = k >> 1; j >= 1; j >>= 1)
                    kk = bitonic_shfl_step(kk, j, (lane & k) == 0, lane);
            }
            int pos = (int)(kk & 0x3FFu);
            float4 b4 = sbox[pos];                     // garbage for lane>=m (guarded below)
            float  ar = (b4.z - b4.x) * (b4.w - b4.y);

            unsigned removed = 0u, keepB = 0u;
            for (int i = 0; i < m; i++) {
                if ((removed >> i) & 1u) continue;     // uniform across warp
                keepB |= 1u << i;
                float wx1 = __shfl_sync(FULL, b4.x, i);
                float wy1 = __shfl_sync(FULL, b4.y, i);
                float wx2 = __shfl_sync(FULL, b4.z, i);
                float wy2 = __shfl_sync(FULL, b4.w, i);
                float wa  = __shfl_sync(FULL, ar,   i);
                float iw = fminf(b4.z, wx2) - fmaxf(b4.x, wx1);
                float ih = fminf(b4.w, wy2) - fmaxf(b4.y, wy1);
                iw = fmaxf(iw, 0.0f);
                ih = fmaxf(ih, 0.0f);
                float inter = iw * ih;
                bool s = (lane > i) && (lane < m) &&
                         (inter > NMS_TH * (ar + wa - inter + 1e-9f));
                removed |= __ballot_sync(FULL, s);
            }
            if (lane < m && ((keepB >> lane) & 1u)) keepS[pos] = 1u;
        } else {
            // generic fallback (rare): iterative select-min + suppress, warp-parallel
            while (true) {
                unsigned long long bestk = ~0ull;
                for (int idx = lane; idx < m; idx += 32)
                    if (state[bs + idx] == 0u) {
                        unsigned long long k2 = list[bs + idx];
                        if (k2 < bestk) bestk = k2;
                    }
                #pragma unroll
                for (int d = 16; d >= 1; d >>= 1) {
                    unsigned long long o = __shfl_xor_sync(FULL, bestk, d);
                    if (o < bestk) bestk = o;
                }
                if (bestk == ~0ull) break;
                int wpos = (int)(bestk & 0x3FFu);
                float4 wb = sbox[wpos];
                float  wa = (wb.z - wb.x) * (wb.w - wb.y);
                for (int idx = lane; idx < m; idx += 32) {
                    if (state[bs + idx] != 0u) continue;
                    unsigned long long k2 = list[bs + idx];
                    if (k2 == bestk) { state[bs + idx] = 1u; keepS[wpos] = 1u; continue; }
                    int p2 = (int)(k2 & 0x3FFu);
                    float4 b2 = sbox[p2];
                    float a2 = (b2.z - b2.x) * (b2.w - b2.y);
                    float iw = fminf(b2.z, wb.z) - fmaxf(b2.x, wb.x);
                    float ih = fminf(b2.w, wb.w) - fmaxf(b2.y, wb.y);
                    iw = fmaxf(iw, 0.0f);
                    ih = fmaxf(ih, 0.0f);
                    float inter = iw * ih;
                    if (inter > NMS_TH * (a2 + wa - inter + 1e-9f)) state[bs + idx] = 2u;
                }
                __syncwarp(FULL);
            }
        }
    }
    __syncthreads();

    // ---------------- keep output (already in original order) ----------------
    out[(size_t)N_IMG * HW * 6 + (size_t)n * HW + t] = (float)keepS[t];
}

extern "C" void kernel_launch(void* const* d_in, const int* in_sizes, int n_in,
                              void* d_out, int out_size)
{
    const float* in = (const float*)d_in[0];
    float* out = (float*)d_out;
    fastestdet_kernel<<<N_IMG, 1024>>>(in, out);
}